// round 4
// baseline (speedup 1.0000x reference)
#include <cuda_runtime.h>

#define N_NODES 50000
#define N_EDGES 800000
#define F_IN    128
#define H_DIM   64
#define C_OUT   40

// ---------------- scratch (device globals; no allocation allowed) ----------
__device__ __align__(16) float g_y1[N_NODES * H_DIM];      // x @ Wl1
__device__ __align__(16) float g_xr[N_NODES * H_DIM];      // x @ Wr1
__device__ __align__(16) float g_xw[N_NODES * H_DIM];      // x @ Wlin[0:128]
__device__ __align__(16) float g_agg1[N_NODES * H_DIM];    // scatter-sum of y1
__device__ __align__(16) float g_cnt[N_NODES];             // in-degree (float)
__device__ __align__(16) float g_hidden[N_NODES * H_DIM];  // relu(l2norm(conv1))
__device__ __align__(16) float g_z[N_NODES * C_OUT];       // h @ Wl2
__device__ __align__(16) float g_hr[N_NODES * C_OUT];      // h @ Wr2
__device__ __align__(16) float g_agg2[N_NODES * C_OUT];    // scatter-sum of z
__device__ __align__(16) int2  g_srcdst[N_EDGES];          // repacked (src,dst)
__device__ int g_is64;                                     // edge dtype flag

// ---------------- helpers ---------------------------------------------------
__device__ __forceinline__ unsigned long long pack2(float a) {
    unsigned long long r;
    asm("mov.b64 %0, {%1, %1};" : "=l"(r) : "f"(a));
    return r;
}
// packed fp32x2 FMA: 2 fp32 FMAs per instruction (sm_100+), exact fp32 numerics
#define FMA2(d, a, b) asm("fma.rn.f32x2 %0, %1, %2, %0;" : "+l"(d) : "l"(a), "l"(b))

// scalar reductions only: sm_103a has no v4 FP red (HW trap 717 observed)
__device__ __forceinline__ void red_add_v4(float* p, float4 v) {
    atomicAdd(p + 0, v.x);
    atomicAdd(p + 1, v.y);
    atomicAdd(p + 2, v.z);
    atomicAdd(p + 3, v.w);
}

// ---------------- dtype probe -------------------------------------------------
// int64 edge values < 50000 -> every odd 32-bit word is 0.
// genuine int32 edge data -> odd words are ~uniform node ids (not all zero).
// Samples stay within the first 1.6M int32 words (valid under BOTH layouts).
__global__ void k_detect(const int* __restrict__ ei32) {
    __shared__ int s_any;
    if (threadIdx.x == 0) s_any = 0;
    __syncthreads();
    int any = 0;
    for (int s = threadIdx.x; s < 4096; s += 256) {
        int i = s * 195;                 // spread over [0, 800000)
        if (ei32[2 * i + 1] != 0) any = 1;
    }
    if (any) atomicOr(&s_any, 1);
    __syncthreads();
    if (threadIdx.x == 0) g_is64 = (s_any == 0);
}

// ---------------- repack edges into int2 (src,dst) ----------------------------
__global__ void k_prep(const int* __restrict__ ei32) {
    int e = blockIdx.x * 256 + threadIdx.x;
    if (e >= N_EDGES) return;
    int2 p;
    if (g_is64) {                        // int64 layout: low word at 2*idx
        p.x = ei32[2 * e];
        p.y = ei32[2 * (N_EDGES + e)];
    } else {                             // int32 layout
        p.x = ei32[e];
        p.y = ei32[N_EDGES + e];
    }
    g_srcdst[e] = p;
}

// ---------------- zero scratch ----------------------------------------------
// agg1: 800,000 f4 ; agg2: 500,000 f4 ; cnt: 12,500 f4
__global__ void k_zero() {
    int idx = blockIdx.x * 256 + threadIdx.x;
    float4 z = make_float4(0.f, 0.f, 0.f, 0.f);
    if (idx < 800000)        ((float4*)g_agg1)[idx] = z;
    else if (idx < 1300000)  ((float4*)g_agg2)[idx - 800000] = z;
    else if (idx < 1312500)  ((float4*)g_cnt)[idx - 1300000] = z;
}

// ---------------- GEMM1: [y1 | xr | xw] = x[N,128] @ W[128,64] (3 weight sets)
__global__ void k_gemm1(const float* __restrict__ x,
                        const float* __restrict__ Wl1,
                        const float* __restrict__ Wr1,
                        const float* __restrict__ Wlin) {
    extern __shared__ float sm[];
    float* xs = sm;               // [64][129]
    float* ws = sm + 64 * 129;    // [128][64]

    int ct = blockIdx.y;
    const float* Wsrc = (ct == 0) ? Wl1 : ((ct == 1) ? Wr1 : Wlin);
    float* out = (ct == 0) ? g_y1 : ((ct == 1) ? g_xr : g_xw);

    int row0 = blockIdx.x * 64;
    int t = threadIdx.x;

    for (int i = t; i < 64 * 32; i += 256) {
        int m = i >> 5, kc = i & 31;
        int r = row0 + m;
        float4 v = (r < N_NODES) ? ((const float4*)x)[r * 32 + kc]
                                 : make_float4(0.f, 0.f, 0.f, 0.f);
        float* d = xs + m * 129 + kc * 4;
        d[0] = v.x; d[1] = v.y; d[2] = v.z; d[3] = v.w;
    }
    for (int i = t; i < 128 * 16; i += 256)
        ((float4*)ws)[i] = ((const float4*)Wsrc)[i];
    __syncthreads();

    int m = t & 63, cg = t >> 6;
    unsigned long long acc[8] = {};
    const float* xrow = xs + m * 129;

#pragma unroll 4
    for (int k = 0; k < 128; k++) {
        unsigned long long a2 = pack2(xrow[k]);
        const ulonglong2* wp = (const ulonglong2*)(ws + k * 64 + cg * 16);
        ulonglong2 b0 = wp[0], b1 = wp[1];
        FMA2(acc[0], a2, b0.x); FMA2(acc[1], a2, b0.y);
        FMA2(acc[2], a2, b1.x); FMA2(acc[3], a2, b1.y);
        b0 = wp[2]; b1 = wp[3];
        FMA2(acc[4], a2, b0.x); FMA2(acc[5], a2, b0.y);
        FMA2(acc[6], a2, b1.x); FMA2(acc[7], a2, b1.y);
    }

    int r = row0 + m;
    if (r < N_NODES) {
        float* f = (float*)acc;
        float4* o = (float4*)(out + r * 64 + cg * 16);
        o[0] = make_float4(f[0],  f[1],  f[2],  f[3]);
        o[1] = make_float4(f[4],  f[5],  f[6],  f[7]);
        o[2] = make_float4(f[8],  f[9],  f[10], f[11]);
        o[3] = make_float4(f[12], f[13], f[14], f[15]);
    }
}

// ---------------- scatter 1: agg1[dst] += y1[src]; cnt[dst] += 1 -------------
__global__ void k_scatter1() {
    int idx = blockIdx.x * 256 + threadIdx.x;   // exactly E*16 threads
    int e = idx >> 4, j = idx & 15;
    int2 sd = g_srcdst[e];
    float4 v = ((const float4*)g_y1)[sd.x * 16 + j];
    red_add_v4(&g_agg1[sd.y * 64 + j * 4], v);
    if (j == 0) atomicAdd(&g_cnt[sd.y], 1.0f);
}

// ---------------- node1: hidden = relu(l2norm(agg1/cnt + bl1 + xr)) ----------
__global__ void k_node1(const float* __restrict__ bl1) {
    int idx = blockIdx.x * 256 + threadIdx.x;   // exactly N*16 threads
    int node = idx >> 4, j = idx & 15;
    float inv = 1.0f / fmaxf(g_cnt[node], 1.0f);
    float4 v  = ((const float4*)g_agg1)[node * 16 + j];
    float4 b  = ((const float4*)bl1)[j];
    float4 xr = ((const float4*)g_xr)[node * 16 + j];
    v.x = v.x * inv + b.x + xr.x;
    v.y = v.y * inv + b.y + xr.y;
    v.z = v.z * inv + b.z + xr.z;
    v.w = v.w * inv + b.w + xr.w;
    float ss = v.x * v.x + v.y * v.y + v.z * v.z + v.w * v.w;
    ss += __shfl_xor_sync(0xffffffffu, ss, 8);
    ss += __shfl_xor_sync(0xffffffffu, ss, 4);
    ss += __shfl_xor_sync(0xffffffffu, ss, 2);
    ss += __shfl_xor_sync(0xffffffffu, ss, 1);
    float sc = 1.0f / fmaxf(sqrtf(ss), 1e-12f);
    float4 h;
    h.x = fmaxf(v.x * sc, 0.f);
    h.y = fmaxf(v.y * sc, 0.f);
    h.z = fmaxf(v.z * sc, 0.f);
    h.w = fmaxf(v.w * sc, 0.f);
    ((float4*)g_hidden)[node * 16 + j] = h;
}

// ---------------- GEMM2 (fused): h = relu(xw + hidden@Wh + blin);
//                  z = h@Wl2 ; hr = h@Wr2
__global__ void k_gemm2(const float* __restrict__ Wlin,
                        const float* __restrict__ blin,
                        const float* __restrict__ Wl2,
                        const float* __restrict__ Wr2) {
    extern __shared__ float sm[];
    float* hd = sm;                 // [64][65]
    float* wh = hd + 64 * 65;       // [64][64]
    float* hs = wh + 64 * 64;       // [64][65]
    float* wc = hs + 64 * 65;       // [64][80]

    int row0 = blockIdx.x * 64;
    int t = threadIdx.x;

    for (int i = t; i < 64 * 16; i += 256) {
        int m = i >> 4, kc = i & 15;
        int r = row0 + m;
        float4 v = (r < N_NODES) ? ((const float4*)g_hidden)[r * 16 + kc]
                                 : make_float4(0.f, 0.f, 0.f, 0.f);
        float* d = hd + m * 65 + kc * 4;
        d[0] = v.x; d[1] = v.y; d[2] = v.z; d[3] = v.w;
    }
    const float* Wh = Wlin + 128 * 64;
    for (int i = t; i < 64 * 16; i += 256)
        ((float4*)wh)[i] = ((const float4*)Wh)[i];
    for (int i = t; i < 64 * 40; i += 256) {
        int k = i / 40, j = i % 40;
        wc[k * 80 + j]      = Wl2[i];
        wc[k * 80 + 40 + j] = Wr2[i];
    }
    __syncthreads();

    int m = t & 63, cg = t >> 6;
    int r = row0 + m;

    // --- phase A
    {
        unsigned long long acc[8] = {};
        const float* hrow = hd + m * 65;
#pragma unroll 4
        for (int k = 0; k < 64; k++) {
            unsigned long long a2 = pack2(hrow[k]);
            const ulonglong2* wp = (const ulonglong2*)(wh + k * 64 + cg * 16);
            ulonglong2 b0 = wp[0], b1 = wp[1];
            FMA2(acc[0], a2, b0.x); FMA2(acc[1], a2, b0.y);
            FMA2(acc[2], a2, b1.x); FMA2(acc[3], a2, b1.y);
            b0 = wp[2]; b1 = wp[3];
            FMA2(acc[4], a2, b0.x); FMA2(acc[5], a2, b0.y);
            FMA2(acc[6], a2, b1.x); FMA2(acc[7], a2, b1.y);
        }
        float* f = (float*)acc;
        float* hout = hs + m * 65 + cg * 16;
        if (r < N_NODES) {
            const float4* xwv = (const float4*)(g_xw + r * 64 + cg * 16);
            const float4* bb  = (const float4*)(blin + cg * 16);
#pragma unroll
            for (int q = 0; q < 4; q++) {
                float4 xv = xwv[q], bv = bb[q];
                hout[q * 4 + 0] = fmaxf(f[q * 4 + 0] + xv.x + bv.x, 0.f);
                hout[q * 4 + 1] = fmaxf(f[q * 4 + 1] + xv.y + bv.y, 0.f);
                hout[q * 4 + 2] = fmaxf(f[q * 4 + 2] + xv.z + bv.z, 0.f);
                hout[q * 4 + 3] = fmaxf(f[q * 4 + 3] + xv.w + bv.w, 0.f);
            }
        } else {
#pragma unroll
            for (int c = 0; c < 16; c++) hout[c] = 0.f;
        }
    }
    __syncthreads();

    // --- phase B
    {
        unsigned long long acc[10] = {};
        const float* hrow = hs + m * 65;
#pragma unroll 4
        for (int k = 0; k < 64; k++) {
            unsigned long long a2 = pack2(hrow[k]);
            const ulonglong2* wp = (const ulonglong2*)(wc + k * 80 + cg * 20);
            ulonglong2 w0 = wp[0], w1 = wp[1];
            FMA2(acc[0], a2, w0.x); FMA2(acc[1], a2, w0.y);
            FMA2(acc[2], a2, w1.x); FMA2(acc[3], a2, w1.y);
            w0 = wp[2]; w1 = wp[3];
            FMA2(acc[4], a2, w0.x); FMA2(acc[5], a2, w0.y);
            FMA2(acc[6], a2, w1.x); FMA2(acc[7], a2, w1.y);
            w0 = wp[4];
            FMA2(acc[8], a2, w0.x); FMA2(acc[9], a2, w0.y);
        }
        if (r < N_NODES) {
            float* f = (float*)acc;
            float* dst = (cg < 2) ? (g_z + r * 40 + cg * 20)
                                  : (g_hr + r * 40 + (cg - 2) * 20);
            float4* d4 = (float4*)dst;
            d4[0] = make_float4(f[0],  f[1],  f[2],  f[3]);
            d4[1] = make_float4(f[4],  f[5],  f[6],  f[7]);
            d4[2] = make_float4(f[8],  f[9],  f[10], f[11]);
            d4[3] = make_float4(f[12], f[13], f[14], f[15]);
            d4[4] = make_float4(f[16], f[17], f[18], f[19]);
        }
    }
}

// ---------------- scatter 2: agg2[dst] += z[src] -----------------------------
__global__ void k_scatter2() {
    int idx = blockIdx.x * 256 + threadIdx.x;   // exactly E*10 threads
    int e = idx / 10, j = idx - e * 10;
    int2 sd = g_srcdst[e];
    float4 v = ((const float4*)g_z)[sd.x * 10 + j];
    red_add_v4(&g_agg2[sd.y * 40 + j * 4], v);
}

// ---------------- node2: out = l2norm(agg2/cnt + bl2 + hr) -------------------
__global__ void k_node2(const float* __restrict__ bl2, float* __restrict__ out) {
    int node = (blockIdx.x * 256 + threadIdx.x) >> 5;
    int lane = threadIdx.x & 31;
    if (node >= N_NODES) return;
    float inv = 1.0f / fmaxf(g_cnt[node], 1.0f);
    const float* a  = g_agg2 + node * 40;
    const float* hr = g_hr + node * 40;
    float v1 = a[lane] * inv + bl2[lane] + hr[lane];
    float v2 = 0.f;
    if (lane < 8) v2 = a[32 + lane] * inv + bl2[32 + lane] + hr[32 + lane];
    float ss = v1 * v1 + v2 * v2;
#pragma unroll
    for (int o = 16; o > 0; o >>= 1) ss += __shfl_xor_sync(0xffffffffu, ss, o);
    float sc = 1.0f / fmaxf(sqrtf(ss), 1e-12f);
    float* op = out + node * 40;
    op[lane] = v1 * sc;
    if (lane < 8) op[32 + lane] = v2 * sc;
}

// ---------------- launch -----------------------------------------------------
extern "C" void kernel_launch(void* const* d_in, const int* in_sizes, int n_in,
                              void* d_out, int out_size) {
    const float* x    = (const float*)d_in[0];
    const int*   ei32 = (const int*)d_in[1];   // raw 32-bit view; layout probed on device
    const float* Wl1  = (const float*)d_in[2];
    const float* bl1  = (const float*)d_in[3];
    const float* Wr1  = (const float*)d_in[4];
    const float* Wlin = (const float*)d_in[5];
    const float* blin = (const float*)d_in[6];
    const float* Wl2  = (const float*)d_in[7];
    const float* bl2  = (const float*)d_in[8];
    const float* Wr2  = (const float*)d_in[9];
    float* out = (float*)d_out;

    const int SMEM1 = (64 * 129 + 128 * 64) * 4;                      // 65,792 B
    const int SMEM2 = (64 * 65 + 64 * 64 + 64 * 65 + 64 * 80) * 4;    // 70,144 B
    cudaFuncSetAttribute(k_gemm1, cudaFuncAttributeMaxDynamicSharedMemorySize, SMEM1);
    cudaFuncSetAttribute(k_gemm2, cudaFuncAttributeMaxDynamicSharedMemorySize, SMEM2);

    k_detect<<<1, 256>>>(ei32);
    k_prep<<<3125, 256>>>(ei32);
    k_zero<<<5128, 256>>>();
    k_gemm1<<<dim3(782, 3), 256, SMEM1>>>(x, Wl1, Wr1, Wlin);
    k_scatter1<<<50000, 256>>>();            // E*16 / 256
    k_node1<<<3125, 256>>>(bl1);             // N*16 / 256
    k_gemm2<<<782, 256, SMEM2>>>(Wlin, blin, Wl2, Wr2);
    k_scatter2<<<31250, 256>>>();            // E*10 / 256
    k_node2<<<6250, 256>>>(bl2, out);        // N*32 / 256
}